// round 17
// baseline (speedup 1.0000x reference)
#include <cuda_runtime.h>
#include <cuda_bf16.h>

#define BB 8
#define DD 4096
#define HH 32
#define HDD 128
#define KVV 512
#define PASTN 8191
#define TOTALN 8192
#define SCALEF 0.08838834764831845f  // 128^-0.5
#define NSC 16   // s-splits for k_ov
#define NKC 16   // k-splits for qabs

// ---------------- scratch ----------------
__device__ float g_cnew[BB * KVV];
__device__ float g_qabs[BB * HH * KVV];        // zero-init, atomic accumulate
__device__ float g_scores[BB * HH * TOTALN];
__device__ float g_ml2[BB * HH * 2];           // (rowmax, 1/rowsum)
__device__ float g_opart[NSC * BB * HH * KVV];
__device__ float g_oc[BB * HH * KVV];
__device__ float g_ohead[BB * HH * HDD];

// packed dual-fp32 FMA (sm_100+)
__device__ __forceinline__ float2 ffma2(const float2 a, const float2 b, const float2 c) {
    float2 d;
    asm("fma.rn.f32x2 %0, %1, %2, %3;"
        : "=l"(*(unsigned long long*)&d)
        : "l"(*(const unsigned long long*)&a),
          "l"(*(const unsigned long long*)&b),
          "l"(*(const unsigned long long*)&c));
    return d;
}
__device__ __forceinline__ float2 ffma2s(const float a, const float2 b, const float2 c) {
    return ffma2(make_float2(a, a), b, c);
}

__device__ __forceinline__ void cp_async16(unsigned s, const void* g) {
    asm volatile("cp.async.cg.shared.global [%0], [%1], 16;" :: "r"(s), "l"(g));
}
__device__ __forceinline__ void cp_commit() {
    asm volatile("cp.async.commit_group;");
}
__device__ __forceinline__ unsigned smaddr(const void* p) {
    unsigned a;
    asm("{.reg .u64 t; cvta.to.shared.u64 t, %1; cvt.u32.u64 %0, t;}" : "=r"(a) : "l"(p));
    return a;
}

// fp32 pair -> packed bf16 hi/lo (hi = rn(x), lo = rn(x - hi))
__device__ __forceinline__ void cvt_hilo(float2 v, unsigned& hi, unsigned& lo) {
    __nv_bfloat16 h0 = __float2bfloat16_rn(v.x);
    __nv_bfloat16 h1 = __float2bfloat16_rn(v.y);
    __nv_bfloat16 l0 = __float2bfloat16_rn(v.x - __bfloat162float(h0));
    __nv_bfloat16 l1 = __float2bfloat16_rn(v.y - __bfloat162float(h1));
    hi = (unsigned)__bfloat16_as_ushort(h0) | ((unsigned)__bfloat16_as_ushort(h1) << 16);
    lo = (unsigned)__bfloat16_as_ushort(l0) | ((unsigned)__bfloat16_as_ushort(l1) << 16);
}

// classic tensor-core mma (sm_80+ PTX, legal on compute_103)
__device__ __forceinline__ void mma16816(float* d, const unsigned* a, const unsigned* b) {
    asm volatile(
        "mma.sync.aligned.m16n8k16.row.col.f32.bf16.bf16.f32 "
        "{%0,%1,%2,%3}, {%4,%5,%6,%7}, {%8,%9}, {%0,%1,%2,%3};"
        : "+f"(d[0]), "+f"(d[1]), "+f"(d[2]), "+f"(d[3])
        : "r"(a[0]), "r"(a[1]), "r"(a[2]), "r"(a[3]), "r"(b[0]), "r"(b[1]));
}

// ---------------- K0: zero d_out, g_cnew, g_ohead, g_qabs ----------------
__global__ void k_init(float* __restrict__ out) {
    int i = blockIdx.x * 256 + threadIdx.x;       // 131072 threads
    g_qabs[i] = 0.f;
    if (i < BB * DD) { out[i] = 0.f; g_ohead[i] = 0.f; }
    if (i < BB * KVV) g_cnew[i] = 0.f;
}

// ---------------- K1: c_new = x @ w_compress (k-split, atomic) ----------------
__global__ __launch_bounds__(256) void k_compress(const float* __restrict__ x,
                                                  const float* __restrict__ wc) {
    __shared__ float xs[128][9];
    int kc = blockIdx.x;
    int tid = threadIdx.x;
    for (int i = tid; i < 1024; i += 256) {
        int k = i >> 3, b = i & 7;
        xs[k][b] = x[b * DD + kc * 128 + k];
    }
    __syncthreads();
    float2 acc[BB];
    #pragma unroll
    for (int b = 0; b < BB; b++) acc[b] = make_float2(0.f, 0.f);
    const float* wp = wc + (size_t)kc * 128 * KVV + tid * 2;
    #pragma unroll 8
    for (int k = 0; k < 128; k++) {
        float2 w2 = *(const float2*)(wp + (size_t)k * KVV);
        float4 x0 = *(const float4*)&xs[k][0];
        float4 x1 = *(const float4*)&xs[k][4];
        acc[0] = ffma2s(x0.x, w2, acc[0]);
        acc[1] = ffma2s(x0.y, w2, acc[1]);
        acc[2] = ffma2s(x0.z, w2, acc[2]);
        acc[3] = ffma2s(x0.w, w2, acc[3]);
        acc[4] = ffma2s(x1.x, w2, acc[4]);
        acc[5] = ffma2s(x1.y, w2, acc[5]);
        acc[6] = ffma2s(x1.z, w2, acc[6]);
        acc[7] = ffma2s(x1.w, w2, acc[7]);
    }
    #pragma unroll
    for (int b = 0; b < BB; b++) {
        atomicAdd(&g_cnew[b * KVV + tid * 2 + 0], acc[b].x);
        atomicAdd(&g_cnew[b * KVV + tid * 2 + 1], acc[b].y);
    }
}

// ---------------- K2: q_abs (scale folded into x), atomic accumulate ----------------
__global__ __launch_bounds__(128) void k_qabs(const float* __restrict__ x,
                                              const float* __restrict__ aqk) {
    __shared__ float xs[256][9];
    int kc = blockIdx.x;
    int h  = blockIdx.y;
    int tid = threadIdx.x;
    for (int i = tid; i < 2048; i += 128) {
        int k = i >> 3, b = i & 7;
        xs[k][b] = x[b * DD + kc * 256 + k] * SCALEF;
    }
    __syncthreads();
    float2 acc[BB][2];
    #pragma unroll
    for (int b = 0; b < BB; b++) {
        acc[b][0] = make_float2(0.f, 0.f);
        acc[b][1] = make_float2(0.f, 0.f);
    }
    const float* ap = aqk + ((size_t)h * DD + (size_t)kc * 256) * KVV + tid * 4;
    #pragma unroll 8
    for (int k = 0; k < 256; k++) {
        float4 a4 = *(const float4*)(ap + (size_t)k * KVV);
        float2 alo = make_float2(a4.x, a4.y);
        float2 ahi = make_float2(a4.z, a4.w);
        float4 x0 = *(const float4*)&xs[k][0];
        float4 x1 = *(const float4*)&xs[k][4];
        acc[0][0] = ffma2s(x0.x, alo, acc[0][0]); acc[0][1] = ffma2s(x0.x, ahi, acc[0][1]);
        acc[1][0] = ffma2s(x0.y, alo, acc[1][0]); acc[1][1] = ffma2s(x0.y, ahi, acc[1][1]);
        acc[2][0] = ffma2s(x0.z, alo, acc[2][0]); acc[2][1] = ffma2s(x0.z, ahi, acc[2][1]);
        acc[3][0] = ffma2s(x0.w, alo, acc[3][0]); acc[3][1] = ffma2s(x0.w, ahi, acc[3][1]);
        acc[4][0] = ffma2s(x1.x, alo, acc[4][0]); acc[4][1] = ffma2s(x1.x, ahi, acc[4][1]);
        acc[5][0] = ffma2s(x1.y, alo, acc[5][0]); acc[5][1] = ffma2s(x1.y, ahi, acc[5][1]);
        acc[6][0] = ffma2s(x1.z, alo, acc[6][0]); acc[6][1] = ffma2s(x1.z, ahi, acc[6][1]);
        acc[7][0] = ffma2s(x1.w, alo, acc[7][0]); acc[7][1] = ffma2s(x1.w, ahi, acc[7][1]);
    }
    #pragma unroll
    for (int b = 0; b < BB; b++) {
        float* dst = &g_qabs[((size_t)b * HH + h) * KVV + tid * 4];
        atomicAdd(dst + 0, acc[b][0].x);
        atomicAdd(dst + 1, acc[b][0].y);
        atomicAdd(dst + 2, acc[b][1].x);
        atomicAdd(dst + 3, acc[b][1].y);
    }
}

// ---------------- K3: scores via mma.sync, ring-4 cp.async, q pre-converted ----------------
// grid (sc=16, b=8); 512 threads = 16 warps; warp owns 32s x 32h; 32 chunks of 16 k.
// smem (floats): stage ring 4 x [512][20] @0 (40960); q_hi/q_lo u32[32][260] @40960/@49280.
#define SG_STG 0
#define SG_SLOT 10240
#define SG_QH 40960
#define SG_QL 49280
#define QW 260
#define SMEM_SC (57600 * 4)   // 230400 B

__device__ __forceinline__ void sc_issue(unsigned sb, const float* __restrict__ past_c,
                                         int b, int S0, int ck, int slot, int tid) {
    #pragma unroll
    for (int t = 0; t < 4; t++) {
        int i = tid + t * 512;
        int s = i >> 2, seg = i & 3;
        const float* row = (S0 + s < PASTN) ? past_c + ((size_t)b * PASTN + S0 + s) * KVV
                                            : g_cnew + b * KVV;
        cp_async16(sb + (unsigned)(SG_STG + slot * SG_SLOT + s * 20 + seg * 4) * 4u,
                   row + ck * 16 + seg * 4);
    }
    cp_commit();
}

__global__ __launch_bounds__(512) void k_scores(const float* __restrict__ past_c) {
    extern __shared__ float sm[];
    unsigned sb = smaddr(sm);
    int sc = blockIdx.x, b = blockIdx.y;
    int tid = threadIdx.x;
    int w = tid >> 5, lane = tid & 31;
    int gid = lane >> 2, tig = lane & 3;
    int S0 = sc * 512;
    int SB = w * 32;
    unsigned* qh = (unsigned*)(sm + SG_QH);
    unsigned* ql = (unsigned*)(sm + SG_QL);

    // precompute q bf16 hi/lo once (8192 float2 over 512 threads)
    #pragma unroll
    for (int t = 0; t < 16; t++) {
        int i = tid + t * 512;
        int h = i >> 8, jp = i & 255;
        float2 v = *(const float2*)&g_qabs[((size_t)b * HH + h) * KVV + jp * 2];
        unsigned hw, lw;
        cvt_hilo(v, hw, lw);
        qh[h * QW + jp] = hw;
        ql[h * QW + jp] = lw;
    }
    // prologue: issue chunks 0,1,2
    sc_issue(sb, past_c, b, S0, 0, 0, tid);
    sc_issue(sb, past_c, b, S0, 1, 1, tid);
    sc_issue(sb, past_c, b, S0, 2, 2, tid);

    float d[2][4][4];
    #pragma unroll
    for (int m = 0; m < 2; m++)
        #pragma unroll
        for (int n = 0; n < 4; n++)
            #pragma unroll
            for (int c = 0; c < 4; c++) d[m][n][c] = 0.f;

    for (int ck = 0; ck < 32; ck++) {
        if (ck < 30)      asm volatile("cp.async.wait_group 2;");
        else if (ck == 30) asm volatile("cp.async.wait_group 1;");
        else               asm volatile("cp.async.wait_group 0;");
        __syncthreads();                       // chunk ck visible; compute ck-1 done
        if (ck < 29)
            sc_issue(sb, past_c, b, S0, ck + 3, (ck + 3) & 3, tid);
        const float* A = sm + SG_STG + (ck & 3) * SG_SLOT;
        unsigned ahi[2][4], alo[2][4], bhi[4][2], blo[4][2];
        #pragma unroll
        for (int m = 0; m < 2; m++) {
            const float* Ar = A + (SB + m * 16 + gid) * 20 + tig * 2;
            cvt_hilo(*(const float2*)(Ar),       ahi[m][0], alo[m][0]);
            cvt_hilo(*(const float2*)(Ar + 160), ahi[m][1], alo[m][1]);
            cvt_hilo(*(const float2*)(Ar + 8),   ahi[m][2], alo[m][2]);
            cvt_hilo(*(const float2*)(Ar + 168), ahi[m][3], alo[m][3]);
        }
        int kw = ck * 8 + tig;
        #pragma unroll
        for (int n = 0; n < 4; n++) {
            int hb = (n * 8 + gid) * QW + kw;
            bhi[n][0] = qh[hb];     blo[n][0] = ql[hb];
            bhi[n][1] = qh[hb + 4]; blo[n][1] = ql[hb + 4];
        }
        #pragma unroll
        for (int m = 0; m < 2; m++)
            #pragma unroll
            for (int n = 0; n < 4; n++) {
                mma16816(d[m][n], ahi[m], bhi[n]);
                mma16816(d[m][n], ahi[m], blo[n]);
                mma16816(d[m][n], alo[m], bhi[n]);
            }
    }

    // epilogue: stage D through smem (warp-private region in stage), coalesced store
    __syncthreads();
    float* outw = sm + SG_STG + w * (32 * 33);
    #pragma unroll
    for (int m = 0; m < 2; m++)
        #pragma unroll
        for (int n = 0; n < 4; n++)
            #pragma unroll
            for (int c = 0; c < 4; c++) {
                int srow = m * 16 + gid + ((c >> 1) << 3);
                int hcol = n * 8 + tig * 2 + (c & 1);
                outw[hcol * 33 + srow] = d[m][n][c];
            }
    __syncwarp();
    #pragma unroll
    for (int h = 0; h < 32; h++)
        g_scores[((size_t)b * HH + h) * TOTALN + S0 + SB + lane] = outw[h * 33 + lane];
}

// ---------------- K4: row stats (m, 1/l) per (b,h) ----------------
__global__ __launch_bounds__(256) void k_mrow() {
    int bh = blockIdx.x;
    int tid = threadIdx.x;
    int w = tid >> 5, lane = tid & 31;
    const float* row = g_scores + (size_t)bh * TOTALN;
    float4 v[8];
    #pragma unroll
    for (int i = 0; i < 8; i++) v[i] = ((const float4*)row)[tid * 8 + i];
    float m = -1e30f;
    #pragma unroll
    for (int i = 0; i < 8; i++)
        m = fmaxf(m, fmaxf(fmaxf(v[i].x, v[i].y), fmaxf(v[i].z, v[i].w)));
    #pragma unroll
    for (int o = 16; o; o >>= 1) m = fmaxf(m, __shfl_xor_sync(0xffffffffu, m, o));
    __shared__ float redm[8], reds[8];
    if (lane == 0) redm[w] = m;
    __syncthreads();
    m = redm[0];
    #pragma unroll
    for (int i = 1; i < 8; i++) m = fmaxf(m, redm[i]);
    float s = 0.f;
    #pragma unroll
    for (int i = 0; i < 8; i++)
        s += __expf(v[i].x - m) + __expf(v[i].y - m) + __expf(v[i].z - m) + __expf(v[i].w - m);
    #pragma unroll
    for (int o = 16; o; o >>= 1) s += __shfl_xor_sync(0xffffffffu, s, o);
    if (lane == 0) reds[w] = s;
    __syncthreads();
    if (tid == 0) {
        s = reds[0] + reds[1] + reds[2] + reds[3] + reds[4] + reds[5] + reds[6] + reds[7];
        g_ml2[bh * 2 + 0] = m;
        g_ml2[bh * 2 + 1] = 1.f / s;
    }
}

// ---------------- K5: o_c partials via mma.sync, ring-3 cp.async ----------------
// grid (sc=16, b=8); 512 threads; warp owns 32h x 32n; 16 chunks of 32 s.
// smem (floats): cb ring 3 x [32][524] @0 (50304); e_hi/e_lo u32[32][20] @50304/@50944.
#define OV_SLOT 16768
#define OV_EH 50304
#define OV_EL 50944
#define EW 20
#define SMEM_OV (51584 * 4)   // 206336 B

__global__ __launch_bounds__(512) void k_ov(const float* __restrict__ past_c) {
    extern __shared__ float sm[];
    __shared__ float msh[HH], ilsh[HH];
    unsigned sb = smaddr(sm);
    int sc = blockIdx.x, b = blockIdx.y;
    int tid = threadIdx.x;
    int w = tid >> 5, lane = tid & 31;
    int gid = lane >> 2, tig = lane & 3;
    int S0 = sc * 512;
    int n0 = w * 32;
    unsigned* eh = (unsigned*)(sm + OV_EH);
    unsigned* el = (unsigned*)(sm + OV_EL);
    if (tid < HH) {
        msh[tid]  = g_ml2[(b * HH + tid) * 2 + 0];
        ilsh[tid] = g_ml2[(b * HH + tid) * 2 + 1];
    }

    // prologue: issue chunks 0,1
    #pragma unroll
    for (int c0 = 0; c0 < 2; c0++) {
        #pragma unroll
        for (int t = 0; t < 8; t++) {
            int i = tid + t * 512;
            int s = i >> 7, n4 = i & 127;
            int sa = S0 + c0 * 32 + s;
            const float* row = (sa < PASTN) ? past_c + ((size_t)b * PASTN + sa) * KVV
                                            : g_cnew + b * KVV;
            cp_async16(sb + (unsigned)(c0 * OV_SLOT + s * 524 + n4 * 4) * 4u, row + n4 * 4);
        }
        cp_commit();
    }

    float d[2][4][4];
    #pragma unroll
    for (int m = 0; m < 2; m++)
        #pragma unroll
        for (int n = 0; n < 4; n++)
            #pragma unroll
            for (int c = 0; c < 4; c++) d[m][n][c] = 0.f;

    for (int ch = 0; ch < 16; ch++) {
        int s0 = S0 + ch * 32;
        if (ch < 15) asm volatile("cp.async.wait_group 1;");
        else         asm volatile("cp.async.wait_group 0;");
        __syncthreads();                   // chunk ch visible; compute ch-1 done
        // e tile: [32h][32s] -> bf16 hi/lo (512 threads, 1 float2 each)
        {
            int h = tid >> 4, sp = tid & 15;
            float2 v = *(const float2*)&g_scores[((size_t)b * HH + h) * TOTALN + s0 + sp * 2];
            float il = ilsh[h], mm = msh[h];
            float2 e2 = make_float2(__expf(v.x - mm) * il, __expf(v.y - mm) * il);
            unsigned hw, lw;
            cvt_hilo(e2, hw, lw);
            eh[h * EW + sp] = hw;
            el[h * EW + sp] = lw;
        }
        if (ch < 14) {                     // issue chunk ch+2 into slot (ch+2)%3
            int s0n = s0 + 64;
            int slot = (ch + 2) % 3;
            #pragma unroll
            for (int t = 0; t < 8; t++) {
                int i = tid + t * 512;
                int s = i >> 7, n4 = i & 127;
                const float* row = (s0n + s < PASTN) ? past_c + ((size_t)b * PASTN + s0n + s) * KVV
                                                     : g_cnew + b * KVV;
                cp_async16(sb + (unsigned)(slot * OV_SLOT + s * 524 + n4 * 4) * 4u, row + n4 * 4);
            }
            cp_commit();
        }
        __syncthreads();                   // e visible
        const float* cbuf = sm + (ch % 3) * OV_SLOT;
        #pragma unroll
        for (int ks = 0; ks < 2; ks++) {
            int k0 = ks * 16;
            unsigned ahi[2][4], alo[2][4], bhi[4][2], blo[4][2];
            #pragma unroll
            for (int m = 0; m < 2; m++) {
                int base = (m * 16 + gid) * EW + ks * 8 + tig;
                ahi[m][0] = eh[base];        alo[m][0] = el[base];
                ahi[m][1] = eh[base + 160];  alo[m][1] = el[base + 160];   // +8 rows
                ahi[m][2] = eh[base + 4];    alo[m][2] = el[base + 4];     // +8 cols
                ahi[m][3] = eh[base + 164];  alo[m][3] = el[base + 164];
            }
            #pragma unroll
            for (int n = 0; n < 4; n++) {
                int nn = n0 + n * 8 + gid;
                int kr = k0 + tig * 2;
                float v0 = cbuf[kr * 524 + nn];
                float v1 = cbuf[(kr + 1) * 524 + nn];
                cvt_hilo(make_float2(v0, v1), bhi[n][0], blo[n][0]);
                float v2 = cbuf[(kr + 8) * 524 + nn];
                float v3 = cbuf[(kr + 9) * 524 + nn];
                cvt_hilo(make_float2(v2, v3), bhi[n][1], blo[n][1]);
            }
            #pragma unroll
            for (int m = 0; m < 2; m++)
                #pragma unroll
                for (int n = 0; n < 4; n++) {
                    mma16816(d[m][n], ahi[m], bhi[n]);
                    mma16816(d[m][n], ahi[m], blo[n]);
                    mma16816(d[m][n], alo[m], bhi[n]);
                }
        }
    }
    // store: warp owns full (h, n0..n0+31) tile — direct float2 stores
    size_t obase = ((size_t)sc * BB + b) * HH * KVV;
    #pragma unroll
    for (int m = 0; m < 2; m++)
        #pragma unroll
        for (int n = 0; n < 4; n++) {
            int row = m * 16 + gid;
            int col = n0 + n * 8 + tig * 2;
            *(float2*)&g_opart[obase + (size_t)row * KVV + col] =
                make_float2(d[m][n][0], d[m][n][1]);
            *(float2*)&g_opart[obase + (size_t)(row + 8) * KVV + col] =
                make_float2(d[m][n][2], d[m][n][3]);
        }
}

// reduce NSC s-partials -> g_oc
__global__ void k_redo() {
    int i = blockIdx.x * 256 + threadIdx.x;
    const float4* p = (const float4*)g_opart;
    float4 s = make_float4(0.f, 0.f, 0.f, 0.f);
    #pragma unroll
    for (int c = 0; c < NSC; c++) {
        float4 t = p[c * 32768 + i];
        s.x += t.x; s.y += t.y; s.z += t.z; s.w += t.w;
    }
    ((float4*)g_oc)[i] = s;
}

// ---------------- K6: per-head v-up (n-split, atomic) ----------------
__global__ __launch_bounds__(128) void k_vup(const float* __restrict__ wv) {
    __shared__ float od[128][9];
    int h = blockIdx.x, nc = blockIdx.y;
    int tid = threadIdx.x;
    int jp = tid & 63, g = tid >> 6;
    for (int i = tid; i < 1024; i += 128) {
        int n = i >> 3, b = i & 7;
        od[n][b] = g_oc[((size_t)b * HH + h) * KVV + nc * 128 + n];
    }
    __syncthreads();
    float2 acc[BB];
    #pragma unroll
    for (int b = 0; b < BB; b++) acc[b] = make_float2(0.f, 0.f);
    const float* wp = wv + (size_t)(nc * 128 + g * 64) * (HH * HDD) + h * HDD + jp * 2;
    #pragma unroll 8
    for (int n = 0; n < 64; n++) {
        float2 w2 = *(const float2*)(wp + (size_t)n * (HH * HDD));
        float4 o0 = *(const float4*)&od[g * 64 + n][0];
        float4 o1 = *(const float4*)&od[g * 64 + n][4];
        acc[0] = ffma2s(o0.x, w2, acc[0]);
        acc[1] = ffma2s(o0.y, w2, acc[1]);
        acc[2] = ffma2s(o0.z, w2, acc[2]);
        acc[3] = ffma2s(o0.w, w2, acc[3]);
        acc[4] = ffma2s(o1.x, w2, acc[4]);
        acc[5] = ffma2s(o1.y, w2, acc[5]);
        acc[6] = ffma2s(o1.z, w2, acc[6]);
        acc[7] = ffma2s(o1.w, w2, acc[7]);
    }
    #pragma unroll
    for (int b = 0; b < BB; b++) {
        atomicAdd(&g_ohead[b * DD + h * HDD + jp * 2 + 0], acc[b].x);
        atomicAdd(&g_ohead[b * DD + h * HDD + jp * 2 + 1], acc[b].y);
    }
}

// ---------------- K7: out = out_head @ w_o (m-split over 16, atomic) ----------------
__global__ __launch_bounds__(128) void k_oproj(const float* __restrict__ wo,
                                               float* __restrict__ out) {
    __shared__ float ohd[256][9];
    int dt = blockIdx.x, mc = blockIdx.y;
    int tid = threadIdx.x;
    for (int i = tid; i < 2048; i += 128) {
        int m = i >> 3, b = i & 7;
        ohd[m][b] = g_ohead[b * DD + mc * 256 + m];
    }
    __syncthreads();
    float2 acc[BB];
    #pragma unroll
    for (int b = 0; b < BB; b++) acc[b] = make_float2(0.f, 0.f);
    const float* wp = wo + (size_t)mc * 256 * DD + dt * 256 + tid * 2;
    #pragma unroll 8
    for (int m = 0; m < 256; m++) {
        float2 w2 = *(const float2*)(wp + (size_t)m * DD);
        float4 o0 = *(const float4*)&ohd[m][0];
        float4 o1 = *(const float4*)&ohd[m][4];
        acc[0] = ffma2s(o0.x, w2, acc[0]);
        acc[1] = ffma2s(o0.y, w2, acc[1]);
        acc[2] = ffma2s(o0.z, w2, acc[2]);
        acc[3] = ffma2s(o0.w, w2, acc[3]);
        acc[4] = ffma2s(o1.x, w2, acc[4]);
        acc[5] = ffma2s(o1.y, w2, acc[5]);
        acc[6] = ffma2s(o1.z, w2, acc[6]);
        acc[7] = ffma2s(o1.w, w2, acc[7]);
    }
    #pragma unroll
    for (int b = 0; b < BB; b++) {
        atomicAdd(&out[b * DD + dt * 256 + tid * 2 + 0], acc[b].x);
        atomicAdd(&out[b * DD + dt * 256 + tid * 2 + 1], acc[b].y);
    }
}

// ---------------- launch ----------------
extern "C" void kernel_launch(void* const* d_in, const int* in_sizes, int n_in,
                              void* d_out, int out_size) {
    const float* x      = (const float*)d_in[0];
    const float* past_c = (const float*)d_in[1];
    const float* aqk    = (const float*)d_in[2];
    const float* wc     = (const float*)d_in[3];
    const float* wv     = (const float*)d_in[4];
    const float* wo     = (const float*)d_in[5];
    float* out = (float*)d_out;

    cudaFuncSetAttribute(k_scores, cudaFuncAttributeMaxDynamicSharedMemorySize, SMEM_SC);
    cudaFuncSetAttribute(k_ov,     cudaFuncAttributeMaxDynamicSharedMemorySize, SMEM_OV);

    k_init<<<512, 256>>>(out);                          // idx 0
    k_compress<<<32, 256>>>(x, wc);                     // idx 1
    k_qabs<<<dim3(NKC, 32), 128>>>(x, aqk);             // idx 2
    k_scores<<<dim3(16, 8), 512, SMEM_SC>>>(past_c);    // idx 3  <- profiled
    k_mrow<<<256, 256>>>();                             // idx 4
    k_ov<<<dim3(NSC, 8), 512, SMEM_OV>>>(past_c);       // idx 5
    k_redo<<<128, 256>>>();                             // idx 6
    k_vup<<<dim3(32, 4), 128>>>(wv);                    // idx 7
    k_oproj<<<dim3(16, 16), 128>>>(wo, out);            // idx 8
}